// round 10
// baseline (speedup 1.0000x reference)
#include <cuda_runtime.h>
#include <cstdint>
#include <cstddef>

// Problem constants
#define T_TOT 16384   // B*S tokens
#define DDIM  1024
#define NEXP  8
#define HDIM  2048
#define NASGN (2 * T_TOT)   // total (token, expert) assignments = 32768

// GEMM tiling
#define BM 128
#define BN 128
#define BK 16
#define PAD 4
#define MAX_TILES (NASGN / BM + NEXP)   // 264

// ---------------------------------------------------------------------------
// Device scratch (allocation-free rule: __device__ globals)
// ---------------------------------------------------------------------------
__device__ int   g_cnt[NEXP];
__device__ int   g_off[NEXP];
__device__ int   g_fill[NEXP];
__device__ int   g_ntiles;
__device__ int   g_tile_e[MAX_TILES];
__device__ int   g_tile_row[MAX_TILES];   // global row index of tile start

__device__ int   g_route_i[T_TOT * 2];    // (i0, i1) per token
__device__ float g_route_w[T_TOT * 2];    // (w0, w1) per token

__device__ int   g_tok[NASGN];            // compacted: token id per slot
__device__ float g_wgt[NASGN];            // gate weight per slot
__device__ int   g_pos[T_TOT * 2];        // token -> its two slots

__device__ float g_H[(size_t)(NASGN + BM) * HDIM];  // 256 MB + pad
__device__ float g_O[(size_t)NASGN * DDIM];         // 128 MB

// ---------------------------------------------------------------------------
__global__ void zero_counts_kernel() {
    if (threadIdx.x < NEXP) g_cnt[threadIdx.x] = 0;
}

// ---------------------------------------------------------------------------
// Router: one warp per token. logits = x . Wg, softmax, top-2, renormalize.
// ---------------------------------------------------------------------------
__global__ __launch_bounds__(256) void router_kernel(const float* __restrict__ x,
                                                     const float* __restrict__ Wg) {
    int t    = (blockIdx.x * blockDim.x + threadIdx.x) >> 5;
    int lane = threadIdx.x & 31;
    if (t >= T_TOT) return;

    const float* xr = x + (size_t)t * DDIM;
    float acc[NEXP];
#pragma unroll
    for (int e = 0; e < NEXP; e++) acc[e] = 0.f;

    for (int d = lane; d < DDIM; d += 32) {
        float xv = xr[d];
        const float* wr = Wg + d * NEXP;
#pragma unroll
        for (int e = 0; e < NEXP; e++) acc[e] += xv * wr[e];
    }
#pragma unroll
    for (int e = 0; e < NEXP; e++) {
#pragma unroll
        for (int o = 16; o > 0; o >>= 1)
            acc[e] += __shfl_xor_sync(0xffffffffu, acc[e], o);
    }

    if (lane == 0) {
        float mx = acc[0];
#pragma unroll
        for (int e = 1; e < NEXP; e++) mx = fmaxf(mx, acc[e]);
        float p[NEXP];
        float Z = 0.f;
#pragma unroll
        for (int e = 0; e < NEXP; e++) { p[e] = __expf(acc[e] - mx); Z += p[e]; }
        float invZ = 1.f / Z;
#pragma unroll
        for (int e = 0; e < NEXP; e++) p[e] *= invZ;

        // top-2 with lowest-index tie-breaking (matches jax.lax.top_k)
        int i0 = 0;
#pragma unroll
        for (int e = 1; e < NEXP; e++) if (p[e] > p[i0]) i0 = e;
        int i1 = (i0 == 0) ? 1 : 0;
#pragma unroll
        for (int e = 0; e < NEXP; e++) {
            if (e == i0) continue;
            if (p[e] > p[i1]) i1 = e;
        }
        float v0 = p[i0], v1 = p[i1];
        float inv = 1.f / (v0 + v1 + 1e-9f);

        g_route_i[2 * t + 0] = i0;
        g_route_i[2 * t + 1] = i1;
        g_route_w[2 * t + 0] = v0 * inv;
        g_route_w[2 * t + 1] = v1 * inv;
        atomicAdd(&g_cnt[i0], 1);
        atomicAdd(&g_cnt[i1], 1);
    }
}

// ---------------------------------------------------------------------------
// Setup: prefix-sum the 8 counts, build the row-tile map. Single thread.
// ---------------------------------------------------------------------------
__global__ void setup_kernel() {
    if (threadIdx.x != 0 || blockIdx.x != 0) return;
    int off = 0, nt = 0;
    for (int e = 0; e < NEXP; e++) {
        g_off[e]  = off;
        g_fill[e] = off;
        int c = g_cnt[e];
        for (int r = 0; r < c; r += BM) {
            g_tile_e[nt]   = e;
            g_tile_row[nt] = off + r;
            nt++;
        }
        off += c;
    }
    g_ntiles = nt;
}

// ---------------------------------------------------------------------------
// Scatter: place each token's two assignments into compact per-expert slots.
// ---------------------------------------------------------------------------
__global__ __launch_bounds__(256) void scatter_kernel() {
    int t = blockIdx.x * blockDim.x + threadIdx.x;
    if (t >= T_TOT) return;
#pragma unroll
    for (int k = 0; k < 2; k++) {
        int   e = g_route_i[2 * t + k];
        float w = g_route_w[2 * t + k];
        int slot = atomicAdd(&g_fill[e], 1);
        g_tok[slot] = t;
        g_wgt[slot] = w;
        g_pos[2 * t + k] = slot;
    }
}

// ---------------------------------------------------------------------------
// FFN layer 1: H[slot] = relu( gather(x)[rows] @ W1[e] + b1[e] )
// Register double-buffered: next chunk's LDGs issue right after the barrier
// and drain behind the 16 k-steps of FFMA.
// ---------------------------------------------------------------------------
__global__ __launch_bounds__(256) void ffn1_kernel(const float* __restrict__ x,
                                                   const float* __restrict__ W1,
                                                   const float* __restrict__ b1) {
    int tile = blockIdx.y;
    if (tile >= g_ntiles) return;
    int e    = g_tile_e[tile];
    int row0 = g_tile_row[tile];
    int valid = g_off[e] + g_cnt[e] - row0;
    if (valid > BM) valid = BM;
    int c0   = blockIdx.x * BN;

    const float* W = W1 + (size_t)e * DDIM * HDIM;

    __shared__ float As[BK][BM + PAD];
    __shared__ float Bs[BK][BN + PAD];
    __shared__ int   toks[BM];

    int tid = threadIdx.x;
    if (tid < BM) toks[tid] = (tid < valid) ? g_tok[row0 + tid] : -1;
    __syncthreads();

    int tx = tid & 15, ty = tid >> 4;
    float acc[8][8];
#pragma unroll
    for (int i = 0; i < 8; i++)
#pragma unroll
        for (int j = 0; j < 8; j++) acc[i][j] = 0.f;

    // loader indices (fixed per thread)
    int ar  = tid >> 2;            // A rows ar and ar+64
    int akq = (tid & 3) << 2;      // k-quad within chunk
    int bk  = tid >> 5;            // B k-rows bk and bk+8
    int bcq = (tid & 31) << 2;     // column quad

    float4 fa0, fa1, fb0, fb1;

    // prologue: load chunk 0 into registers
    {
        int tok0 = toks[ar];
        fa0 = (tok0 >= 0) ? *(const float4*)(x + (size_t)tok0 * DDIM + akq)
                          : make_float4(0.f, 0.f, 0.f, 0.f);
        int tok1 = toks[ar + 64];
        fa1 = (tok1 >= 0) ? *(const float4*)(x + (size_t)tok1 * DDIM + akq)
                          : make_float4(0.f, 0.f, 0.f, 0.f);
        fb0 = *(const float4*)(W + (size_t)bk * HDIM + c0 + bcq);
        fb1 = *(const float4*)(W + (size_t)(bk + 8) * HDIM + c0 + bcq);
    }

    for (int k0 = 0; k0 < DDIM; k0 += BK) {
        // stage current chunk from registers
        As[akq + 0][ar] = fa0.x; As[akq + 1][ar] = fa0.y;
        As[akq + 2][ar] = fa0.z; As[akq + 3][ar] = fa0.w;
        As[akq + 0][ar + 64] = fa1.x; As[akq + 1][ar + 64] = fa1.y;
        As[akq + 2][ar + 64] = fa1.z; As[akq + 3][ar + 64] = fa1.w;
        *(float4*)&Bs[bk][bcq]     = fb0;
        *(float4*)&Bs[bk + 8][bcq] = fb1;
        __syncthreads();

        // issue next chunk's loads (drain behind compute)
        if (k0 + BK < DDIM) {
            int kn = k0 + BK;
            int tok0 = toks[ar];
            fa0 = (tok0 >= 0) ? *(const float4*)(x + (size_t)tok0 * DDIM + kn + akq)
                              : make_float4(0.f, 0.f, 0.f, 0.f);
            int tok1 = toks[ar + 64];
            fa1 = (tok1 >= 0) ? *(const float4*)(x + (size_t)tok1 * DDIM + kn + akq)
                              : make_float4(0.f, 0.f, 0.f, 0.f);
            fb0 = *(const float4*)(W + (size_t)(kn + bk) * HDIM + c0 + bcq);
            fb1 = *(const float4*)(W + (size_t)(kn + bk + 8) * HDIM + c0 + bcq);
        }

#pragma unroll
        for (int k = 0; k < BK; k++) {
            float a[8], b[8];
            *(float4*)&a[0] = *(float4*)&As[k][ty * 4];
            *(float4*)&a[4] = *(float4*)&As[k][ty * 4 + 64];
            *(float4*)&b[0] = *(float4*)&Bs[k][tx * 4];
            *(float4*)&b[4] = *(float4*)&Bs[k][tx * 4 + 64];
#pragma unroll
            for (int i = 0; i < 8; i++)
#pragma unroll
                for (int j = 0; j < 8; j++) acc[i][j] += a[i] * b[j];
        }
        __syncthreads();
    }

    // Epilogue: +b1, ReLU, store to g_H
#pragma unroll
    for (int i = 0; i < 8; i++) {
        int r = ty * 4 + (i & 3) + (i >> 2) * 64;
        if (r >= valid) continue;
        size_t slot = (size_t)(row0 + r);
#pragma unroll
        for (int jh = 0; jh < 2; jh++) {
            int c = c0 + tx * 4 + jh * 64;
            float4 bb = *(const float4*)(b1 + (size_t)e * HDIM + c);
            float4 o;
            o.x = fmaxf(acc[i][jh * 4 + 0] + bb.x, 0.f);
            o.y = fmaxf(acc[i][jh * 4 + 1] + bb.y, 0.f);
            o.z = fmaxf(acc[i][jh * 4 + 2] + bb.z, 0.f);
            o.w = fmaxf(acc[i][jh * 4 + 3] + bb.w, 0.f);
            *(float4*)(g_H + slot * HDIM + c) = o;
        }
    }
}

// ---------------------------------------------------------------------------
// FFN layer 2: O[slot] = w[slot] * ( H[rows] @ W2[e] + b2[e] )
// Same register double-buffering.
// ---------------------------------------------------------------------------
__global__ __launch_bounds__(256) void ffn2_kernel(const float* __restrict__ W2,
                                                   const float* __restrict__ b2) {
    int tile = blockIdx.y;
    if (tile >= g_ntiles) return;
    int e    = g_tile_e[tile];
    int row0 = g_tile_row[tile];
    int valid = g_off[e] + g_cnt[e] - row0;
    if (valid > BM) valid = BM;
    int c0   = blockIdx.x * BN;

    const float* W = W2 + (size_t)e * HDIM * DDIM;
    const float* A = g_H + (size_t)row0 * HDIM;   // rows beyond valid: pad, never stored

    __shared__ float As[BK][BM + PAD];
    __shared__ float Bs[BK][BN + PAD];

    int tid = threadIdx.x;
    int tx = tid & 15, ty = tid >> 4;
    float acc[8][8];
#pragma unroll
    for (int i = 0; i < 8; i++)
#pragma unroll
        for (int j = 0; j < 8; j++) acc[i][j] = 0.f;

    int ar  = tid >> 2;
    int akq = (tid & 3) << 2;
    int bk  = tid >> 5;
    int bcq = (tid & 31) << 2;

    float4 fa0, fa1, fb0, fb1;
    {
        fa0 = *(const float4*)(A + (size_t)ar * HDIM + akq);
        fa1 = *(const float4*)(A + (size_t)(ar + 64) * HDIM + akq);
        fb0 = *(const float4*)(W + (size_t)bk * DDIM + c0 + bcq);
        fb1 = *(const float4*)(W + (size_t)(bk + 8) * DDIM + c0 + bcq);
    }

    for (int k0 = 0; k0 < HDIM; k0 += BK) {
        As[akq + 0][ar] = fa0.x; As[akq + 1][ar] = fa0.y;
        As[akq + 2][ar] = fa0.z; As[akq + 3][ar] = fa0.w;
        As[akq + 0][ar + 64] = fa1.x; As[akq + 1][ar + 64] = fa1.y;
        As[akq + 2][ar + 64] = fa1.z; As[akq + 3][ar + 64] = fa1.w;
        *(float4*)&Bs[bk][bcq]     = fb0;
        *(float4*)&Bs[bk + 8][bcq] = fb1;
        __syncthreads();

        if (k0 + BK < HDIM) {
            int kn = k0 + BK;
            fa0 = *(const float4*)(A + (size_t)ar * HDIM + kn + akq);
            fa1 = *(const float4*)(A + (size_t)(ar + 64) * HDIM + kn + akq);
            fb0 = *(const float4*)(W + (size_t)(kn + bk) * DDIM + c0 + bcq);
            fb1 = *(const float4*)(W + (size_t)(kn + bk + 8) * DDIM + c0 + bcq);
        }

#pragma unroll
        for (int k = 0; k < BK; k++) {
            float a[8], b[8];
            *(float4*)&a[0] = *(float4*)&As[k][ty * 4];
            *(float4*)&a[4] = *(float4*)&As[k][ty * 4 + 64];
            *(float4*)&b[0] = *(float4*)&Bs[k][tx * 4];
            *(float4*)&b[4] = *(float4*)&Bs[k][tx * 4 + 64];
#pragma unroll
            for (int i = 0; i < 8; i++)
#pragma unroll
                for (int j = 0; j < 8; j++) acc[i][j] += a[i] * b[j];
        }
        __syncthreads();
    }

#pragma unroll
    for (int i = 0; i < 8; i++) {
        int r = ty * 4 + (i & 3) + (i >> 2) * 64;
        if (r >= valid) continue;
        size_t slot = (size_t)(row0 + r);
        float w = g_wgt[slot];
#pragma unroll
        for (int jh = 0; jh < 2; jh++) {
            int c = c0 + tx * 4 + jh * 64;
            float4 bb = *(const float4*)(b2 + (size_t)e * DDIM + c);
            float4 o;
            o.x = w * (acc[i][jh * 4 + 0] + bb.x);
            o.y = w * (acc[i][jh * 4 + 1] + bb.y);
            o.z = w * (acc[i][jh * 4 + 2] + bb.z);
            o.w = w * (acc[i][jh * 4 + 3] + bb.w);
            *(float4*)(g_O + slot * DDIM + c) = o;
        }
    }
}

// ---------------------------------------------------------------------------
// Combine: y[t] = O[pos[2t]] + O[pos[2t+1]]  (gate weights already applied)
// ---------------------------------------------------------------------------
__global__ __launch_bounds__(256) void combine_kernel(float* __restrict__ y) {
    int t  = blockIdx.x;
    int s0 = g_pos[2 * t + 0];
    int s1 = g_pos[2 * t + 1];
    int d  = threadIdx.x * 4;   // 256 * 4 = 1024 = DDIM
    float4 a = *(const float4*)(g_O + (size_t)s0 * DDIM + d);
    float4 b = *(const float4*)(g_O + (size_t)s1 * DDIM + d);
    float4 o = make_float4(a.x + b.x, a.y + b.y, a.z + b.z, a.w + b.w);
    *(float4*)(y + (size_t)t * DDIM + d) = o;
}

// ---------------------------------------------------------------------------
// Launch
// ---------------------------------------------------------------------------
extern "C" void kernel_launch(void* const* d_in, const int* in_sizes, int n_in,
                              void* d_out, int out_size) {
    const float* x  = (const float*)d_in[0];
    const float* Wg = (const float*)d_in[1];
    const float* W1 = (const float*)d_in[2];
    const float* b1 = (const float*)d_in[3];
    const float* W2 = (const float*)d_in[4];
    const float* b2 = (const float*)d_in[5];
    float* y = (float*)d_out;

    zero_counts_kernel<<<1, 32>>>();
    router_kernel<<<T_TOT / 8, 256>>>(x, Wg);
    setup_kernel<<<1, 1>>>();
    scatter_kernel<<<T_TOT / 256, 256>>>();
    ffn1_kernel<<<dim3(HDIM / BN, MAX_TILES), 256>>>(x, W1, b1);
    ffn2_kernel<<<dim3(DDIM / BN, MAX_TILES), 256>>>(W2, b2);
    combine_kernel<<<T_TOT, 256>>>(y);
}

// round 12
// speedup vs baseline: 1.1693x; 1.1693x over previous
#include <cuda_runtime.h>
#include <cstdint>
#include <cstddef>

// Problem constants
#define T_TOT 16384   // B*S tokens
#define DDIM  1024
#define NEXP  8
#define HDIM  2048
#define NASGN (2 * T_TOT)   // total (token, expert) assignments = 32768

// GEMM tiling
#define BM 128
#define BN 128
#define BK 16
#define PAD 4
#define MAX_TILES (NASGN / BM + NEXP)   // 264

// Packed fp32x2 FMA (sm_100+): d = a*b + d per 32-bit lane of a 64-bit pair.
#define FMA_F32X2(acc, aa, bb) \
    asm("fma.rn.f32x2 %0, %1, %2, %0;" : "+l"(acc) : "l"(aa), "l"(bb))
#define DUP_F32X2(dst, s) \
    asm("mov.b64 %0, {%1, %1};" : "=l"(dst) : "f"(s))
#define UNPACK_F32X2(lo, hi, p) \
    asm("mov.b64 {%0, %1}, %2;" : "=f"(lo), "=f"(hi) : "l"(p))

// ---------------------------------------------------------------------------
// Device scratch (allocation-free rule: __device__ globals)
// ---------------------------------------------------------------------------
__device__ int   g_cnt[NEXP];
__device__ int   g_off[NEXP];
__device__ int   g_fill[NEXP];
__device__ int   g_ntiles;
__device__ int   g_tile_e[MAX_TILES];
__device__ int   g_tile_row[MAX_TILES];   // global row index of tile start

__device__ int   g_route_i[T_TOT * 2];    // (i0, i1) per token
__device__ float g_route_w[T_TOT * 2];    // (w0, w1) per token

__device__ int   g_tok[NASGN];            // compacted: token id per slot
__device__ float g_wgt[NASGN];            // gate weight per slot
__device__ int   g_pos[T_TOT * 2];        // token -> its two slots

__device__ float g_H[(size_t)(NASGN + BM) * HDIM];  // 256 MB + pad
__device__ float g_O[(size_t)NASGN * DDIM];         // 128 MB

// ---------------------------------------------------------------------------
__global__ void zero_counts_kernel() {
    if (threadIdx.x < NEXP) g_cnt[threadIdx.x] = 0;
}

// ---------------------------------------------------------------------------
// Router: one warp per token. logits = x . Wg, softmax, top-2, renormalize.
// ---------------------------------------------------------------------------
__global__ __launch_bounds__(256) void router_kernel(const float* __restrict__ x,
                                                     const float* __restrict__ Wg) {
    int t    = (blockIdx.x * blockDim.x + threadIdx.x) >> 5;
    int lane = threadIdx.x & 31;
    if (t >= T_TOT) return;

    const float* xr = x + (size_t)t * DDIM;
    float acc[NEXP];
#pragma unroll
    for (int e = 0; e < NEXP; e++) acc[e] = 0.f;

    for (int d = lane; d < DDIM; d += 32) {
        float xv = xr[d];
        const float* wr = Wg + d * NEXP;
#pragma unroll
        for (int e = 0; e < NEXP; e++) acc[e] += xv * wr[e];
    }
#pragma unroll
    for (int e = 0; e < NEXP; e++) {
#pragma unroll
        for (int o = 16; o > 0; o >>= 1)
            acc[e] += __shfl_xor_sync(0xffffffffu, acc[e], o);
    }

    if (lane == 0) {
        float mx = acc[0];
#pragma unroll
        for (int e = 1; e < NEXP; e++) mx = fmaxf(mx, acc[e]);
        float p[NEXP];
        float Z = 0.f;
#pragma unroll
        for (int e = 0; e < NEXP; e++) { p[e] = __expf(acc[e] - mx); Z += p[e]; }
        float invZ = 1.f / Z;
#pragma unroll
        for (int e = 0; e < NEXP; e++) p[e] *= invZ;

        // top-2 with lowest-index tie-breaking (matches jax.lax.top_k)
        int i0 = 0;
#pragma unroll
        for (int e = 1; e < NEXP; e++) if (p[e] > p[i0]) i0 = e;
        int i1 = (i0 == 0) ? 1 : 0;
#pragma unroll
        for (int e = 0; e < NEXP; e++) {
            if (e == i0) continue;
            if (p[e] > p[i1]) i1 = e;
        }
        float v0 = p[i0], v1 = p[i1];
        float inv = 1.f / (v0 + v1 + 1e-9f);

        g_route_i[2 * t + 0] = i0;
        g_route_i[2 * t + 1] = i1;
        g_route_w[2 * t + 0] = v0 * inv;
        g_route_w[2 * t + 1] = v1 * inv;
        atomicAdd(&g_cnt[i0], 1);
        atomicAdd(&g_cnt[i1], 1);
    }
}

// ---------------------------------------------------------------------------
// Setup: prefix-sum the 8 counts, build the row-tile map. Single thread.
// ---------------------------------------------------------------------------
__global__ void setup_kernel() {
    if (threadIdx.x != 0 || blockIdx.x != 0) return;
    int off = 0, nt = 0;
    for (int e = 0; e < NEXP; e++) {
        g_off[e]  = off;
        g_fill[e] = off;
        int c = g_cnt[e];
        for (int r = 0; r < c; r += BM) {
            g_tile_e[nt]   = e;
            g_tile_row[nt] = off + r;
            nt++;
        }
        off += c;
    }
    g_ntiles = nt;
}

// ---------------------------------------------------------------------------
// Scatter: place each token's two assignments into compact per-expert slots.
// ---------------------------------------------------------------------------
__global__ __launch_bounds__(256) void scatter_kernel() {
    int t = blockIdx.x * blockDim.x + threadIdx.x;
    if (t >= T_TOT) return;
#pragma unroll
    for (int k = 0; k < 2; k++) {
        int   e = g_route_i[2 * t + k];
        float w = g_route_w[2 * t + k];
        int slot = atomicAdd(&g_fill[e], 1);
        g_tok[slot] = t;
        g_wgt[slot] = w;
        g_pos[2 * t + k] = slot;
    }
}

// ---------------------------------------------------------------------------
// FFN layer 1: H[slot] = relu( gather(x)[rows] @ W1[e] + b1[e] )
// Inner product uses packed fp32x2 FMA: 32 fma.f32x2 + 8 dup per k-step
// instead of 64 scalar FFMA. Bitwise-identical arithmetic per lane.
// ---------------------------------------------------------------------------
__global__ __launch_bounds__(256) void ffn1_kernel(const float* __restrict__ x,
                                                   const float* __restrict__ W1,
                                                   const float* __restrict__ b1) {
    int tile = blockIdx.y;
    if (tile >= g_ntiles) return;
    int e    = g_tile_e[tile];
    int row0 = g_tile_row[tile];
    int valid = g_off[e] + g_cnt[e] - row0;
    if (valid > BM) valid = BM;
    int c0   = blockIdx.x * BN;

    const float* W = W1 + (size_t)e * DDIM * HDIM;

    __shared__ __align__(16) float As[BK][BM + PAD];
    __shared__ __align__(16) float Bs[BK][BN + PAD];
    __shared__ int toks[BM];

    int tid = threadIdx.x;
    if (tid < BM) toks[tid] = (tid < valid) ? g_tok[row0 + tid] : -1;
    __syncthreads();

    int tx = tid & 15, ty = tid >> 4;
    unsigned long long acc2[8][4];
#pragma unroll
    for (int i = 0; i < 8; i++)
#pragma unroll
        for (int j = 0; j < 4; j++) acc2[i][j] = 0ull;

    for (int k0 = 0; k0 < DDIM; k0 += BK) {
        // A tile: BM x BK, gathered rows of x, float4 along k
#pragma unroll
        for (int i = 0; i < 2; i++) {
            int v  = tid + i * 256;      // 512 vec4 total
            int r  = v >> 2;             // BK/4 = 4 vecs per row
            int kq = (v & 3) << 2;
            int tok = toks[r];
            float4 f = (tok >= 0)
                ? *(const float4*)(x + (size_t)tok * DDIM + k0 + kq)
                : make_float4(0.f, 0.f, 0.f, 0.f);
            As[kq + 0][r] = f.x; As[kq + 1][r] = f.y;
            As[kq + 2][r] = f.z; As[kq + 3][r] = f.w;
        }
        // B tile: BK x BN from W1[e], contiguous in columns
#pragma unroll
        for (int i = 0; i < 2; i++) {
            int v  = tid + i * 256;
            int k  = v >> 5;             // BN/4 = 32 vecs per k-row
            int cq = (v & 31) << 2;
            *(float4*)&Bs[k][cq] =
                *(const float4*)(W + (size_t)(k0 + k) * HDIM + c0 + cq);
        }
        __syncthreads();

#pragma unroll
        for (int k = 0; k < BK; k++) {
            float a[8];
            unsigned long long b2[4];
            *(float4*)&a[0] = *(float4*)&As[k][ty * 4];
            *(float4*)&a[4] = *(float4*)&As[k][ty * 4 + 64];
            *(ulonglong2*)&b2[0] = *(ulonglong2*)&Bs[k][tx * 4];
            *(ulonglong2*)&b2[2] = *(ulonglong2*)&Bs[k][tx * 4 + 64];
#pragma unroll
            for (int i = 0; i < 8; i++) {
                unsigned long long ad;
                DUP_F32X2(ad, a[i]);
                FMA_F32X2(acc2[i][0], ad, b2[0]);
                FMA_F32X2(acc2[i][1], ad, b2[1]);
                FMA_F32X2(acc2[i][2], ad, b2[2]);
                FMA_F32X2(acc2[i][3], ad, b2[3]);
            }
        }
        __syncthreads();
    }

    // Epilogue: +b1, ReLU, store to g_H
#pragma unroll
    for (int i = 0; i < 8; i++) {
        int r  = ty * 4 + (i & 3) + (i >> 2) * 64;
        if (r >= valid) continue;
        size_t slot = (size_t)(row0 + r);
#pragma unroll
        for (int jh = 0; jh < 2; jh++) {
            int c = c0 + tx * 4 + jh * 64;
            float4 bb = *(const float4*)(b1 + (size_t)e * HDIM + c);
            float v0, v1, v2, v3;
            UNPACK_F32X2(v0, v1, acc2[i][jh * 2 + 0]);
            UNPACK_F32X2(v2, v3, acc2[i][jh * 2 + 1]);
            float4 o;
            o.x = fmaxf(v0 + bb.x, 0.f);
            o.y = fmaxf(v1 + bb.y, 0.f);
            o.z = fmaxf(v2 + bb.z, 0.f);
            o.w = fmaxf(v3 + bb.w, 0.f);
            *(float4*)(g_H + slot * HDIM + c) = o;
        }
    }
}

// ---------------------------------------------------------------------------
// FFN layer 2: O[slot] = w[slot] * ( H[rows] @ W2[e] + b2[e] )
// ---------------------------------------------------------------------------
__global__ __launch_bounds__(256) void ffn2_kernel(const float* __restrict__ W2,
                                                   const float* __restrict__ b2) {
    int tile = blockIdx.y;
    if (tile >= g_ntiles) return;
    int e    = g_tile_e[tile];
    int row0 = g_tile_row[tile];
    int valid = g_off[e] + g_cnt[e] - row0;
    if (valid > BM) valid = BM;
    int c0   = blockIdx.x * BN;

    const float* W = W2 + (size_t)e * HDIM * DDIM;
    const float* A = g_H + (size_t)row0 * HDIM;   // rows beyond valid: pad, never stored

    __shared__ __align__(16) float As[BK][BM + PAD];
    __shared__ __align__(16) float Bs[BK][BN + PAD];

    int tid = threadIdx.x;
    int tx = tid & 15, ty = tid >> 4;
    unsigned long long acc2[8][4];
#pragma unroll
    for (int i = 0; i < 8; i++)
#pragma unroll
        for (int j = 0; j < 4; j++) acc2[i][j] = 0ull;

    for (int k0 = 0; k0 < HDIM; k0 += BK) {
#pragma unroll
        for (int i = 0; i < 2; i++) {
            int v  = tid + i * 256;
            int r  = v >> 2;
            int kq = (v & 3) << 2;
            float4 f = *(const float4*)(A + (size_t)r * HDIM + k0 + kq);
            As[kq + 0][r] = f.x; As[kq + 1][r] = f.y;
            As[kq + 2][r] = f.z; As[kq + 3][r] = f.w;
        }
#pragma unroll
        for (int i = 0; i < 2; i++) {
            int v  = tid + i * 256;
            int k  = v >> 5;
            int cq = (v & 31) << 2;
            *(float4*)&Bs[k][cq] =
                *(const float4*)(W + (size_t)(k0 + k) * DDIM + c0 + cq);
        }
        __syncthreads();

#pragma unroll
        for (int k = 0; k < BK; k++) {
            float a[8];
            unsigned long long b2v[4];
            *(float4*)&a[0] = *(float4*)&As[k][ty * 4];
            *(float4*)&a[4] = *(float4*)&As[k][ty * 4 + 64];
            *(ulonglong2*)&b2v[0] = *(ulonglong2*)&Bs[k][tx * 4];
            *(ulonglong2*)&b2v[2] = *(ulonglong2*)&Bs[k][tx * 4 + 64];
#pragma unroll
            for (int i = 0; i < 8; i++) {
                unsigned long long ad;
                DUP_F32X2(ad, a[i]);
                FMA_F32X2(acc2[i][0], ad, b2v[0]);
                FMA_F32X2(acc2[i][1], ad, b2v[1]);
                FMA_F32X2(acc2[i][2], ad, b2v[2]);
                FMA_F32X2(acc2[i][3], ad, b2v[3]);
            }
        }
        __syncthreads();
    }

#pragma unroll
    for (int i = 0; i < 8; i++) {
        int r = ty * 4 + (i & 3) + (i >> 2) * 64;
        if (r >= valid) continue;
        size_t slot = (size_t)(row0 + r);
        float w = g_wgt[slot];
#pragma unroll
        for (int jh = 0; jh < 2; jh++) {
            int c = c0 + tx * 4 + jh * 64;
            float4 bb = *(const float4*)(b2 + (size_t)e * DDIM + c);
            float v0, v1, v2, v3;
            UNPACK_F32X2(v0, v1, acc2[i][jh * 2 + 0]);
            UNPACK_F32X2(v2, v3, acc2[i][jh * 2 + 1]);
            float4 o;
            o.x = w * (v0 + bb.x);
            o.y = w * (v1 + bb.y);
            o.z = w * (v2 + bb.z);
            o.w = w * (v3 + bb.w);
            *(float4*)(g_O + slot * DDIM + c) = o;
        }
    }
}

// ---------------------------------------------------------------------------
// Combine: y[t] = O[pos[2t]] + O[pos[2t+1]]  (gate weights already applied)
// ---------------------------------------------------------------------------
__global__ __launch_bounds__(256) void combine_kernel(float* __restrict__ y) {
    int t  = blockIdx.x;
    int s0 = g_pos[2 * t + 0];
    int s1 = g_pos[2 * t + 1];
    int d  = threadIdx.x * 4;   // 256 * 4 = 1024 = DDIM
    float4 a = *(const float4*)(g_O + (size_t)s0 * DDIM + d);
    float4 b = *(const float4*)(g_O + (size_t)s1 * DDIM + d);
    float4 o = make_float4(a.x + b.x, a.y + b.y, a.z + b.z, a.w + b.w);
    *(float4*)(y + (size_t)t * DDIM + d) = o;
}

// ---------------------------------------------------------------------------
// Launch
// ---------------------------------------------------------------------------
extern "C" void kernel_launch(void* const* d_in, const int* in_sizes, int n_in,
                              void* d_out, int out_size) {
    const float* x  = (const float*)d_in[0];
    const float* Wg = (const float*)d_in[1];
    const float* W1 = (const float*)d_in[2];
    const float* b1 = (const float*)d_in[3];
    const float* W2 = (const float*)d_in[4];
    const float* b2 = (const float*)d_in[5];
    float* y = (float*)d_out;

    zero_counts_kernel<<<1, 32>>>();
    router_kernel<<<T_TOT / 8, 256>>>(x, Wg);
    setup_kernel<<<1, 1>>>();
    scatter_kernel<<<T_TOT / 256, 256>>>();
    ffn1_kernel<<<dim3(HDIM / BN, MAX_TILES), 256>>>(x, W1, b1);
    ffn2_kernel<<<dim3(DDIM / BN, MAX_TILES), 256>>>(W2, b2);
    combine_kernel<<<T_TOT, 256>>>(y);
}